// round 16
// baseline (speedup 1.0000x reference)
#include <cuda_runtime.h>
#include <cuda_fp16.h>
#include <math.h>
#include <stdint.h>

#define B 2048
#define C1 15
#define C2 30
#define P1 29
#define P2 11
#define FC1_IN (30*11*11)
#define FC1_OUT 200
#define KSPLIT 8
#define NKS1 227              // ceil(3630/16)
#define NKS2 53               // ceil(105/2) conv2 row-pair k-steps
#define NFC1 (NKS1*25*32)     // fc1 frag elements

typedef uint16_t u16;
typedef uint32_t u32;

// ---------------- warp mma m16n8k16 fp16 -> f32 ----------------
__device__ __forceinline__ void mma_f16(float* d, u32 a0, u32 a1, u32 a2, u32 a3,
                                        u32 b0, u32 b1) {
    asm volatile(
        "mma.sync.aligned.m16n8k16.row.col.f32.f16.f16.f32 "
        "{%0,%1,%2,%3}, {%4,%5,%6,%7}, {%8,%9}, {%0,%1,%2,%3};"
        : "+f"(d[0]), "+f"(d[1]), "+f"(d[2]), "+f"(d[3])
        : "r"(a0), "r"(a1), "r"(a2), "r"(a3), "r"(b0), "r"(b1));
}

__device__ __forceinline__ u16 f16_bits(float v) {
    return __half_as_ushort(__float2half(v));
}

// ---------------- scratch ----------------
__device__ float g_fc1p[KSPLIT * B * FC1_OUT];
__device__ __align__(4)  u16  g_p2h[B * FC1_IN + 64];           // conv2 out, fp16
__device__ __align__(16) uint2 g_Bfrag2[NKS2 * 4 * 32];         // conv2 W frags
__device__ __align__(16) uint2 g_B1frag[2 * 4 * 32];            // conv1 W frags
__device__ __align__(16) uint2 g_W1frag[NKS1 * 25 * 32];        // fc1 W frags

// ---------------- kernel 0: prep ALL weight fragments ----------------
__global__ void prep_all_frags(const float* __restrict__ w1,
                               const float* __restrict__ w2,
                               const float* __restrict__ wf)
{
    int idx = blockIdx.x * 256 + threadIdx.x;

    if (idx < NFC1) {
        int lane = idx & 31;
        int nt = (idx >> 5) % 25;
        int ks = idx / (25 * 32);
        int o = nt * 8 + (lane >> 2);
        int k0 = ks * 16 + (lane & 3) * 2;
        const float* wr = wf + (size_t)o * FC1_IN;
        float v[4];
        v[0] = (k0     < FC1_IN) ? wr[k0]     : 0.f;
        v[1] = (k0 + 1 < FC1_IN) ? wr[k0 + 1] : 0.f;
        v[2] = (k0 + 8 < FC1_IN) ? wr[k0 + 8] : 0.f;
        v[3] = (k0 + 9 < FC1_IN) ? wr[k0 + 9] : 0.f;
        uint2 q;
        q.x = (u32)f16_bits(v[0]) | ((u32)f16_bits(v[1]) << 16);
        q.y = (u32)f16_bits(v[2]) | ((u32)f16_bits(v[3]) << 16);
        g_W1frag[idx] = q;
        return;
    }
    idx -= NFC1;
    if (idx < NKS2 * 128) {
        int lane = idx & 31, nt = (idx >> 5) & 3, ks = idx >> 7;
        int oc = nt * 8 + (lane >> 2), k0 = (lane & 3) * 2;
        int rA = 2 * ks, rB = rA + 1;
        float v[4] = {0.f, 0.f, 0.f, 0.f};
        if (oc < C2) {
            int icA = rA / 7, dyA = rA % 7;
            const float* wa = w2 + ((oc * C1 + icA) * 7 + dyA) * 7;
            v[0] = wa[k0];
            if (k0 + 1 < 7) v[1] = wa[k0 + 1];
            if (rB <= 104) {
                int icB = rB / 7, dyB = rB % 7;
                const float* wb = w2 + ((oc * C1 + icB) * 7 + dyB) * 7;
                v[2] = wb[k0];
                if (k0 + 1 < 7) v[3] = wb[k0 + 1];
            }
        }
        uint2 q;
        q.x = (u32)f16_bits(v[0]) | ((u32)f16_bits(v[1]) << 16);
        q.y = (u32)f16_bits(v[2]) | ((u32)f16_bits(v[3]) << 16);
        g_Bfrag2[idx] = q;
        return;
    }
    idx -= NKS2 * 128;
    if (idx < 256) {
        int lane = idx & 31, ks = (idx >> 5) & 3, nt = idx >> 7;
        int oc = nt * 8 + (lane >> 2), k0 = (lane & 3) * 2;
        int dy0 = ks * 2, dy1 = dy0 + 1;
        float v[4] = {0.f, 0.f, 0.f, 0.f};
        if (oc < C1) {
            const float* wb = w1 + oc * 49;
            v[0] = wb[dy0 * 7 + k0];
            if (k0 + 1 < 7) v[1] = wb[dy0 * 7 + k0 + 1];
            if (dy1 < 7) {
                v[2] = wb[dy1 * 7 + k0];
                if (k0 + 1 < 7) v[3] = wb[dy1 * 7 + k0 + 1];
            }
        }
        uint2 q;
        q.x = (u32)f16_bits(v[0]) | ((u32)f16_bits(v[1]) << 16);
        q.y = (u32)f16_bits(v[2]) | ((u32)f16_bits(v[3]) << 16);
        g_B1frag[(nt * 4 + ks) * 32 + lane] = q;
    }
}

// ---------------- kernel 1: fused PCEN + conv1 + conv2 + pools (3 CTA/SM) ----------------
// smem: conv2 planes [0,55680) | conv1 planes [55680,72576) | consts
#define PL1 2112                 // u32 per conv1 parity copy
#define PL2 6960                 // u32 per conv2 parity copy
#define MM_P    0
#define MM_C1P  55680
#define MM_SC1  72576
#define MM_SH1  72640
#define MM_SC2  72704
#define MM_SH2  72832
#define MM_RT   72960
#define MM_TOT  73472

__global__ __launch_bounds__(256, 3) void conv_fused_kernel(
    const float* __restrict__ x,
    const float* __restrict__ log_s, const float* __restrict__ log_alpha,
    const float* __restrict__ log_delta, const float* __restrict__ log_r,
    const float* __restrict__ b1,
    const float* __restrict__ g1,  const float* __restrict__ be1,
    const float* __restrict__ mu1, const float* __restrict__ va1,
    const float* __restrict__ b2,
    const float* __restrict__ g2,  const float* __restrict__ be2,
    const float* __restrict__ mu2, const float* __restrict__ va2)
{
    extern __shared__ __align__(16) char smem[];
    u16* pP16 = (u16*)(smem + MM_P);             // conv2 planes (even @0, odd @13920)
    const u32* pH2 = (const u32*)(smem + MM_P);
    u16* c1E16 = (u16*)(smem + MM_C1P);
    u16* c1O16 = c1E16 + 4224;
    const u32* pH1 = (const u32*)(smem + MM_C1P);
    float* sc1 = (float*)(smem + MM_SC1);
    float* sh1 = (float*)(smem + MM_SH1);
    float* sc2 = (float*)(smem + MM_SC2);
    float* sh2 = (float*)(smem + MM_SH2);
    int* rowTab = (int*)(smem + MM_RT);

    const int b = blockIdx.x, t = threadIdx.x;
    const int w = t >> 5, lane = t & 31;

    // ---- phase 0: zero planes + consts ----
    {
        uint4* pz = (uint4*)(smem + MM_P);
        uint4 z = make_uint4(0u, 0u, 0u, 0u);
        for (int i = t; i < 3480; i += 256) pz[i] = z;   // conv2 planes
    }
    if (t < 128) {                                        // conv1 plane tails
        c1E16[4096 + t] = 0;
        c1O16[4095 + t] = 0;
        if (t == 0) c1O16[4223] = 0;
    }
    if (t < 16) {
        if (t < C1) {
            float inv = g1[t] * rsqrtf(va1[t] + 1e-5f);
            sc1[t] = inv;
            sh1[t] = (b1[t] - mu1[t]) * inv + be1[t];
        } else { sc1[t] = 0.f; sh1[t] = 0.f; }
    }
    if (t >= 32 && t < 32 + C2) {
        int c = t - 32;
        float inv = g2[c] * rsqrtf(va2[c] + 1e-5f);
        sc2[c] = inv;
        sh2[c] = (b2[c] - mu2[c]) * inv + be2[c];
    }
    if (t >= 64 && t < 170) {
        int i = t - 64;
        int r = (i < 105) ? i : 104;
        rowTab[i] = ((r / 7) * 29 + (r % 7)) * 16;
    }
    uint2 qf[2][4];
    #pragma unroll
    for (int nt = 0; nt < 2; nt++)
        #pragma unroll
        for (int ks = 0; ks < 4; ks++)
            qf[nt][ks] = g_B1frag[(nt * 4 + ks) * 32 + lane];

    // ---- phase 1: PCEN from gmem registers -> conv1 fp16 planes ----
    {
        const float s     = expf(log_s[0]);
        const float alpha = expf(log_alpha[0]);
        const float delta = expf(log_delta[0]);
        const float r     = expf(log_r[0]);
        const float oms   = 1.0f - s;
        const float dr    = powf(delta, r);
        const float oms16 = powf(oms, 16.0f);
        const float oms32 = oms16 * oms16;

        const int row = t >> 2, seg = t & 3;
        const float* xs = x + (size_t)b * 4096 + row * 64 + seg * 16;
        float xa[16];
        #pragma unroll
        for (int q = 0; q < 4; q++) {
            float4 v = ((const float4*)xs)[q];
            xa[4*q] = v.x; xa[4*q+1] = v.y; xa[4*q+2] = v.z; xa[4*q+3] = v.w;
        }
        float m = 0.0f;
        #pragma unroll
        for (int i = 0; i < 16; i++) m = oms * m + s * xa[i];

        float up1 = __shfl_up_sync(0xFFFFFFFFu, m, 1);
        if (seg >= 1) m += oms16 * up1;
        float up2 = __shfl_up_sync(0xFFFFFFFFu, m, 2);
        if (seg >= 2) m += oms32 * up2;
        float m_in = __shfl_up_sync(0xFFFFFFFFu, m, 1);
        if (seg == 0) m_in = 0.0f;

        const int base = row * 64 + seg * 16;
        m = m_in;
        #pragma unroll 4
        for (int i = 0; i < 16; i++) {
            float xv = xa[i];
            m = oms * m + s * xv;
            float Ma = __powf(m + 1e-6f, alpha);
            u16 h = f16_bits(__powf(__fdividef(xv, Ma) + delta, r) - dr);
            c1E16[base + i] = h;
            if (base + i > 0) c1O16[base + i - 1] = h;
        }
    }
    __syncthreads();

    // ---- phase 2: conv1 MMA + BN/ReLU/pool -> conv2 planes ----
    {
        const int r = lane >> 2;
        const int koff = (lane & 3) * 2;
        for (int mt = w; mt < 232; mt += 8) {
            const int py = mt >> 3, xo = mt & 7;
            const int y0 = 2 * py, x0 = xo * 8;
            const int eA = y0 * 64 + x0 + r + koff;
            int i0 = (eA & 1) * PL1 + (eA >> 1);

            float acc[2][4];
            #pragma unroll
            for (int nt = 0; nt < 2; nt++)
                { acc[nt][0]=0.f; acc[nt][1]=0.f; acc[nt][2]=0.f; acc[nt][3]=0.f; }

            u32 hA = pH1[i0];
            #pragma unroll
            for (int ks = 0; ks < 4; ks++) {
                u32 hB = pH1[i0 + 32];
                u32 hC = pH1[i0 + 64];
                #pragma unroll
                for (int nt = 0; nt < 2; nt++)
                    mma_f16(acc[nt], hA, hB, hB, hC, qf[nt][ks].x, qf[nt][ks].y);
                hA = hC;
                i0 += 64;
            }

            #pragma unroll
            for (int nt = 0; nt < 2; nt++) {
                int oc = nt * 8 + (lane & 3) * 2;
                float s0 = sc1[oc], h0 = sh1[oc];
                float s1 = sc1[oc + 1], h1 = sh1[oc + 1];
                float m0 = fmaxf(fmaxf(acc[nt][0] * s0 + h0, 0.f),
                                 fmaxf(acc[nt][2] * s0 + h0, 0.f));
                float m1 = fmaxf(fmaxf(acc[nt][1] * s1 + h1, 0.f),
                                 fmaxf(acc[nt][3] * s1 + h1, 0.f));
                m0 = fmaxf(m0, __shfl_xor_sync(0xFFFFFFFFu, m0, 4));
                m1 = fmaxf(m1, __shfl_xor_sync(0xFFFFFFFFu, m1, 4));
                if (!(r & 1)) {
                    int px = (x0 + r) >> 1;
                    if (px < P1) {
                        if (oc < C1) {
                            int e = oc * 928 + py * 32 + px;
                            u16 hv = f16_bits(m0);
                            pP16[e] = hv;
                            if (e > 0) pP16[13920 + e - 1] = hv;
                        }
                        if (oc + 1 < C1) {
                            int e = (oc + 1) * 928 + py * 32 + px;
                            u16 hv = f16_bits(m1);
                            pP16[e] = hv;
                            pP16[13920 + e - 1] = hv;
                        }
                    }
                }
            }
        }
    }
    __syncthreads();

    // ---- phase 3: conv2 MMA, m-tile = 2 rows x 8 cols, fused pool ----
    {
        const int r = lane >> 2;
        const int koff = (lane & 3) * 2;
        u16* dst = g_p2h + (size_t)b * FC1_IN;

        for (int mt = w; mt < 33; mt += 8) {
            const int py = mt / 3, xo = mt - py * 3;
            const int px0 = xo * 8 + r;
            const int par = px0 & 1;
            const int o0 = par * PL2 + (2 * py) * 16 + ((px0 + koff - par) >> 1);

            float acc[4][4];
            #pragma unroll
            for (int n = 0; n < 4; n++)
                { acc[n][0]=0.f; acc[n][1]=0.f; acc[n][2]=0.f; acc[n][3]=0.f; }

            uint2 q0 = g_Bfrag2[0 * 32 + lane];
            uint2 q1 = g_Bfrag2[1 * 32 + lane];
            uint2 q2 = g_Bfrag2[2 * 32 + lane];
            uint2 q3 = g_Bfrag2[3 * 32 + lane];

            #pragma unroll 1
            for (int j = 0; j < NKS2; j++) {
                const int kbA = rowTab[2 * j];
                const int kbB = rowTab[2 * j + 1];
                uint2 n0, n1, n2, n3;
                if (j + 1 < NKS2) {
                    n0 = g_Bfrag2[((j + 1) * 4 + 0) * 32 + lane];
                    n1 = g_Bfrag2[((j + 1) * 4 + 1) * 32 + lane];
                    n2 = g_Bfrag2[((j + 1) * 4 + 2) * 32 + lane];
                    n3 = g_Bfrag2[((j + 1) * 4 + 3) * 32 + lane];
                }
                u32 ah0 = pH2[o0 + kbA], ah1 = pH2[o0 + 16 + kbA];
                u32 ah2 = pH2[o0 + kbB], ah3 = pH2[o0 + 16 + kbB];
                mma_f16(acc[0], ah0, ah1, ah2, ah3, q0.x, q0.y);
                mma_f16(acc[1], ah0, ah1, ah2, ah3, q1.x, q1.y);
                mma_f16(acc[2], ah0, ah1, ah2, ah3, q2.x, q2.y);
                mma_f16(acc[3], ah0, ah1, ah2, ah3, q3.x, q3.y);
                q0 = n0; q1 = n1; q2 = n2; q3 = n3;
            }

            // BN + ReLU + 2x2 pool (vertical in-thread, horizontal shfl)
            const int pxp = px0 >> 1;
            const bool wr = ((r & 1) == 0) && (px0 <= 21);
            #pragma unroll
            for (int n = 0; n < 4; n++) {
                int oc = n * 8 + (lane & 3) * 2;
                float s0 = (oc < C2) ? sc2[oc] : 0.f;
                float h0 = (oc < C2) ? sh2[oc] : 0.f;
                float s1 = (oc + 1 < C2) ? sc2[oc + 1] : 0.f;
                float h1 = (oc + 1 < C2) ? sh2[oc + 1] : 0.f;
                float m0 = fmaxf(fmaxf(acc[n][0] * s0 + h0, 0.f),
                                 fmaxf(acc[n][2] * s0 + h0, 0.f));
                float m1 = fmaxf(fmaxf(acc[n][1] * s1 + h1, 0.f),
                                 fmaxf(acc[n][3] * s1 + h1, 0.f));
                m0 = fmaxf(m0, __shfl_xor_sync(0xFFFFFFFFu, m0, 4));
                m1 = fmaxf(m1, __shfl_xor_sync(0xFFFFFFFFu, m1, 4));
                if (wr && oc < C2) {
                    dst[oc * 121 + py * 11 + pxp]       = f16_bits(m0);
                    dst[(oc + 1) * 121 + py * 11 + pxp] = f16_bits(m1);
                }
            }
        }
    }
}

// ---------------- kernel 2: FC1 via fp16 mma (1-term, K-split 8) ----------------
__global__ __launch_bounds__(256, 1) void fc1_mma_kernel()
{
    const int t = threadIdx.x, w = t >> 5, lane = t & 31;
    const int mt = blockIdx.x;
    const int kz = blockIdx.y;

    const int row0 = mt * 128 + w * 16 + (lane >> 2);
    const size_t base0 = (size_t)row0 * FC1_IN;
    const size_t base1 = (size_t)(row0 + 8) * FC1_IN;
    const int koff = (lane & 3) * 2;

    const int ks0 = kz * 28 + (kz < 3 ? kz : 3);
    const int nks = 28 + (kz < 3 ? 1 : 0);

    float acc[25][4];
    #pragma unroll
    for (int n = 0; n < 25; n++)
        { acc[n][0]=0.f; acc[n][1]=0.f; acc[n][2]=0.f; acc[n][3]=0.f; }

    #pragma unroll 1
    for (int ks = ks0; ks < ks0 + nks; ks++) {
        const int k0 = ks * 16 + koff;
        u32 ah0 = *(const u32*)&g_p2h[base0 + k0];
        u32 ah1 = *(const u32*)&g_p2h[base1 + k0];
        u32 ah2 = *(const u32*)&g_p2h[base0 + k0 + 8];
        u32 ah3 = *(const u32*)&g_p2h[base1 + k0 + 8];
        const uint2* bp = &g_W1frag[(size_t)ks * 25 * 32 + lane];
        #pragma unroll
        for (int n = 0; n < 25; n++) {
            uint2 q = bp[n * 32];
            mma_f16(acc[n], ah0, ah1, ah2, ah3, q.x, q.y);
        }
    }

    float* dst = g_fc1p + (size_t)kz * B * FC1_OUT;
    const int r0 = row0, r1 = row0 + 8;
    #pragma unroll
    for (int n = 0; n < 25; n++) {
        int o = n * 8 + (lane & 3) * 2;
        dst[(size_t)r0 * FC1_OUT + o]     = acc[n][0];
        dst[(size_t)r0 * FC1_OUT + o + 1] = acc[n][1];
        dst[(size_t)r1 * FC1_OUT + o]     = acc[n][2];
        dst[(size_t)r1 * FC1_OUT + o + 1] = acc[n][3];
    }
}

// ---------------- kernel 3: FC2 + sigmoid ----------------
__global__ __launch_bounds__(256) void fc2_kernel(
    const float* __restrict__ fc1b,
    const float* __restrict__ w2, const float* __restrict__ b2,
    float* __restrict__ out)
{
    const int warp = threadIdx.x >> 5, lane = threadIdx.x & 31;
    const int b = blockIdx.x * 8 + warp;
    const size_t PS = (size_t)B * FC1_OUT;
    const float* base = g_fc1p + (size_t)b * FC1_OUT;
    float s0 = 0.f, s1 = 0.f;
    for (int o = lane; o < FC1_OUT; o += 32) {
        float v = fc1b[o];
        #pragma unroll
        for (int p = 0; p < KSPLIT; p++)
            v += base[p * PS + o];
        v = fmaxf(v, 0.f);
        s0 += v * w2[o];
        s1 += v * w2[FC1_OUT + o];
    }
    #pragma unroll
    for (int d = 16; d > 0; d >>= 1) {
        s0 += __shfl_xor_sync(0xFFFFFFFFu, s0, d);
        s1 += __shfl_xor_sync(0xFFFFFFFFu, s1, d);
    }
    if (lane == 0) {
        out[2 * b + 0] = 1.f / (1.f + expf(-(s0 + b2[0])));
        out[2 * b + 1] = 1.f / (1.f + expf(-(s1 + b2[1])));
    }
}

// ---------------- launch ----------------
extern "C" void kernel_launch(void* const* d_in, const int* in_sizes, int n_in,
                              void* d_out, int out_size)
{
    const float* x       = (const float*)d_in[0];
    const float* log_s   = (const float*)d_in[1];
    const float* log_a   = (const float*)d_in[2];
    const float* log_d   = (const float*)d_in[3];
    const float* log_r   = (const float*)d_in[4];
    const float* conv1_w = (const float*)d_in[5];
    const float* conv1_b = (const float*)d_in[6];
    const float* bn1_g   = (const float*)d_in[7];
    const float* bn1_b   = (const float*)d_in[8];
    const float* bn1_m   = (const float*)d_in[9];
    const float* bn1_v   = (const float*)d_in[10];
    const float* conv2_w = (const float*)d_in[11];
    const float* conv2_b = (const float*)d_in[12];
    const float* bn2_g   = (const float*)d_in[13];
    const float* bn2_b   = (const float*)d_in[14];
    const float* bn2_m   = (const float*)d_in[15];
    const float* bn2_v   = (const float*)d_in[16];
    const float* fc1_w   = (const float*)d_in[17];
    const float* fc1_b   = (const float*)d_in[18];
    const float* fc2_w   = (const float*)d_in[19];
    const float* fc2_b   = (const float*)d_in[20];
    float* out = (float*)d_out;

    static int smem_set = 0;
    if (!smem_set) {
        cudaFuncSetAttribute(conv_fused_kernel,
                             cudaFuncAttributeMaxDynamicSharedMemorySize, MM_TOT);
        smem_set = 1;
    }

    const int prep_total = NFC1 + NKS2 * 128 + 256;
    prep_all_frags<<<(prep_total + 255) / 256, 256>>>(conv1_w, conv2_w, fc1_w);
    conv_fused_kernel<<<B, 256, MM_TOT>>>(x, log_s, log_a, log_d, log_r,
                                          conv1_b, bn1_g, bn1_b, bn1_m, bn1_v,
                                          conv2_b, bn2_g, bn2_b, bn2_m, bn2_v);
    fc1_mma_kernel<<<dim3(16, KSPLIT), 256>>>();
    fc2_kernel<<<B / 8, 256>>>(fc1_b, fc2_w, fc2_b, out);
}

// round 17
// speedup vs baseline: 1.3581x; 1.3581x over previous
#include <cuda_runtime.h>
#include <cuda_fp16.h>
#include <math.h>
#include <stdint.h>

#define B 2048
#define C1 15
#define C2 30
#define P1 29
#define P2 11
#define FC1_IN (30*11*11)
#define FC1_OUT 200
#define KSPLIT 8
#define NKS1 227              // ceil(3630/16)
#define NKS2 53               // ceil(105/2) conv2 row-pair k-steps
#define NFC1 (NKS1*25*32)     // fc1 frag elements

typedef uint16_t u16;
typedef uint32_t u32;

// ---------------- warp mma m16n8k16 fp16 -> f32 ----------------
__device__ __forceinline__ void mma_f16(float* d, u32 a0, u32 a1, u32 a2, u32 a3,
                                        u32 b0, u32 b1) {
    asm volatile(
        "mma.sync.aligned.m16n8k16.row.col.f32.f16.f16.f32 "
        "{%0,%1,%2,%3}, {%4,%5,%6,%7}, {%8,%9}, {%0,%1,%2,%3};"
        : "+f"(d[0]), "+f"(d[1]), "+f"(d[2]), "+f"(d[3])
        : "r"(a0), "r"(a1), "r"(a2), "r"(a3), "r"(b0), "r"(b1));
}

__device__ __forceinline__ u16 f16_bits(float v) {
    return __half_as_ushort(__float2half(v));
}
__device__ __forceinline__ float f16_val(u16 b) {
    return __half2float(__ushort_as_half(b));
}

// ---------------- scratch ----------------
__device__ float g_fc1p[KSPLIT * B * FC1_OUT];
__device__ __align__(4)  u16  g_p2h[B * FC1_IN + 64];           // conv2 out, fp16
__device__ __align__(16) uint2 g_Bfrag2[NKS2 * 4 * 32];         // conv2 W frags
__device__ __align__(16) uint2 g_B1frag[2 * 4 * 32];            // conv1 W frags
__device__ __align__(16) uint2 g_W1frag[NKS1 * 25 * 32];        // fc1 W frags

// ---------------- kernel 0: prep ALL weight fragments ----------------
__global__ void prep_all_frags(const float* __restrict__ w1,
                               const float* __restrict__ w2,
                               const float* __restrict__ wf)
{
    int idx = blockIdx.x * 256 + threadIdx.x;

    if (idx < NFC1) {
        int lane = idx & 31;
        int nt = (idx >> 5) % 25;
        int ks = idx / (25 * 32);
        int o = nt * 8 + (lane >> 2);
        int k0 = ks * 16 + (lane & 3) * 2;
        const float* wr = wf + (size_t)o * FC1_IN;
        float v[4];
        v[0] = (k0     < FC1_IN) ? wr[k0]     : 0.f;
        v[1] = (k0 + 1 < FC1_IN) ? wr[k0 + 1] : 0.f;
        v[2] = (k0 + 8 < FC1_IN) ? wr[k0 + 8] : 0.f;
        v[3] = (k0 + 9 < FC1_IN) ? wr[k0 + 9] : 0.f;
        uint2 q;
        q.x = (u32)f16_bits(v[0]) | ((u32)f16_bits(v[1]) << 16);
        q.y = (u32)f16_bits(v[2]) | ((u32)f16_bits(v[3]) << 16);
        g_W1frag[idx] = q;
        return;
    }
    idx -= NFC1;
    if (idx < NKS2 * 128) {
        int lane = idx & 31, nt = (idx >> 5) & 3, ks = idx >> 7;
        int oc = nt * 8 + (lane >> 2), k0 = (lane & 3) * 2;
        int rA = 2 * ks, rB = rA + 1;
        float v[4] = {0.f, 0.f, 0.f, 0.f};
        if (oc < C2) {
            int icA = rA / 7, dyA = rA % 7;
            const float* wa = w2 + ((oc * C1 + icA) * 7 + dyA) * 7;
            v[0] = wa[k0];
            if (k0 + 1 < 7) v[1] = wa[k0 + 1];
            if (rB <= 104) {
                int icB = rB / 7, dyB = rB % 7;
                const float* wb = w2 + ((oc * C1 + icB) * 7 + dyB) * 7;
                v[2] = wb[k0];
                if (k0 + 1 < 7) v[3] = wb[k0 + 1];
            }
        }
        uint2 q;
        q.x = (u32)f16_bits(v[0]) | ((u32)f16_bits(v[1]) << 16);
        q.y = (u32)f16_bits(v[2]) | ((u32)f16_bits(v[3]) << 16);
        g_Bfrag2[idx] = q;
        return;
    }
    idx -= NKS2 * 128;
    if (idx < 256) {
        int lane = idx & 31, ks = (idx >> 5) & 3, nt = idx >> 7;
        int oc = nt * 8 + (lane >> 2), k0 = (lane & 3) * 2;
        int dy0 = ks * 2, dy1 = dy0 + 1;
        float v[4] = {0.f, 0.f, 0.f, 0.f};
        if (oc < C1) {
            const float* wb = w1 + oc * 49;
            v[0] = wb[dy0 * 7 + k0];
            if (k0 + 1 < 7) v[1] = wb[dy0 * 7 + k0 + 1];
            if (dy1 < 7) {
                v[2] = wb[dy1 * 7 + k0];
                if (k0 + 1 < 7) v[3] = wb[dy1 * 7 + k0 + 1];
            }
        }
        uint2 q;
        q.x = (u32)f16_bits(v[0]) | ((u32)f16_bits(v[1]) << 16);
        q.y = (u32)f16_bits(v[2]) | ((u32)f16_bits(v[3]) << 16);
        g_B1frag[(nt * 4 + ks) * 32 + lane] = q;
    }
}

// ---------------- kernel 1: fused PCEN + conv1 + conv2 + pools ----------------
// smem: conv2 planes [0,55680) | conv1 planes [55680,72576) | consts
#define PL1 2112                 // u32 per conv1 parity copy
#define PL2 6960                 // u32 per conv2 parity copy
#define MM_P    0
#define MM_C1P  55680
#define MM_SC1  72576
#define MM_SH1  72640
#define MM_SC2  72704
#define MM_SH2  72832
#define MM_RT   72960
#define MM_TOT  73472

__global__ __launch_bounds__(256, 2) void conv_fused_kernel(
    const float* __restrict__ x,
    const float* __restrict__ log_s, const float* __restrict__ log_alpha,
    const float* __restrict__ log_delta, const float* __restrict__ log_r,
    const float* __restrict__ b1,
    const float* __restrict__ g1,  const float* __restrict__ be1,
    const float* __restrict__ mu1, const float* __restrict__ va1,
    const float* __restrict__ b2,
    const float* __restrict__ g2,  const float* __restrict__ be2,
    const float* __restrict__ mu2, const float* __restrict__ va2)
{
    extern __shared__ __align__(16) char smem[];
    u16* pP16 = (u16*)(smem + MM_P);             // conv2 planes (even @0, odd @13920)
    const u32* pH2 = (const u32*)(smem + MM_P);
    u16* c1E16 = (u16*)(smem + MM_C1P);
    u16* c1O16 = c1E16 + 4224;
    const u32* pH1 = (const u32*)(smem + MM_C1P);
    float* sc1 = (float*)(smem + MM_SC1);
    float* sh1 = (float*)(smem + MM_SH1);
    float* sc2 = (float*)(smem + MM_SC2);
    float* sh2 = (float*)(smem + MM_SH2);
    int* rowTab = (int*)(smem + MM_RT);

    const int b = blockIdx.x, t = threadIdx.x;
    const int w = t >> 5, lane = t & 31;

    // ---- phase 0: zero planes + consts ----
    {
        uint4* pz = (uint4*)(smem + MM_P);
        uint4 z = make_uint4(0u, 0u, 0u, 0u);
        for (int i = t; i < 3480; i += 256) pz[i] = z;   // conv2 planes
    }
    if (t < 128) {                                        // conv1 plane tails
        c1E16[4096 + t] = 0;
        c1O16[4095 + t] = 0;
        if (t == 0) c1O16[4223] = 0;
    }
    if (t < 16) {
        if (t < C1) {
            float inv = g1[t] * rsqrtf(va1[t] + 1e-5f);
            sc1[t] = inv;
            sh1[t] = (b1[t] - mu1[t]) * inv + be1[t];
        } else { sc1[t] = 0.f; sh1[t] = 0.f; }
    }
    if (t >= 32 && t < 32 + C2) {
        int c = t - 32;
        float inv = g2[c] * rsqrtf(va2[c] + 1e-5f);
        sc2[c] = inv;
        sh2[c] = (b2[c] - mu2[c]) * inv + be2[c];
    }
    if (t >= 64 && t < 170) {
        int i = t - 64;
        int r = (i < 105) ? i : 104;
        rowTab[i] = ((r / 7) * 29 + (r % 7)) * 16;
    }
    uint2 qf[2][4];
    #pragma unroll
    for (int nt = 0; nt < 2; nt++)
        #pragma unroll
        for (int ks = 0; ks < 4; ks++)
            qf[nt][ks] = g_B1frag[(nt * 4 + ks) * 32 + lane];

    // ---- phase 1: PCEN from gmem registers -> conv1 fp16 planes ----
    {
        const float s     = expf(log_s[0]);
        const float alpha = expf(log_alpha[0]);
        const float delta = expf(log_delta[0]);
        const float r     = expf(log_r[0]);
        const float oms   = 1.0f - s;
        const float dr    = powf(delta, r);
        const float oms16 = powf(oms, 16.0f);
        const float oms32 = oms16 * oms16;

        const int row = t >> 2, seg = t & 3;
        const float* xs = x + (size_t)b * 4096 + row * 64 + seg * 16;
        float xa[16];
        #pragma unroll
        for (int q = 0; q < 4; q++) {
            float4 v = ((const float4*)xs)[q];
            xa[4*q] = v.x; xa[4*q+1] = v.y; xa[4*q+2] = v.z; xa[4*q+3] = v.w;
        }
        float m = 0.0f;
        #pragma unroll
        for (int i = 0; i < 16; i++) m = oms * m + s * xa[i];

        float up1 = __shfl_up_sync(0xFFFFFFFFu, m, 1);
        if (seg >= 1) m += oms16 * up1;
        float up2 = __shfl_up_sync(0xFFFFFFFFu, m, 2);
        if (seg >= 2) m += oms32 * up2;
        float m_in = __shfl_up_sync(0xFFFFFFFFu, m, 1);
        if (seg == 0) m_in = 0.0f;

        const int base = row * 64 + seg * 16;
        m = m_in;
        #pragma unroll 4
        for (int i = 0; i < 16; i++) {
            float xv = xa[i];
            m = oms * m + s * xv;
            float Ma = __powf(m + 1e-6f, alpha);
            u16 h = f16_bits(__powf(__fdividef(xv, Ma) + delta, r) - dr);
            c1E16[base + i] = h;
            if (base + i > 0) c1O16[base + i - 1] = h;
        }
    }
    __syncthreads();

    // ---- phase 2: conv1 MMA + BN/ReLU/pool -> conv2 planes ----
    {
        const int r = lane >> 2;
        const int koff = (lane & 3) * 2;
        for (int mt = w; mt < 232; mt += 8) {
            const int py = mt >> 3, xo = mt & 7;
            const int y0 = 2 * py, x0 = xo * 8;
            const int eA = y0 * 64 + x0 + r + koff;
            int i0 = (eA & 1) * PL1 + (eA >> 1);

            float acc[2][4];
            #pragma unroll
            for (int nt = 0; nt < 2; nt++)
                { acc[nt][0]=0.f; acc[nt][1]=0.f; acc[nt][2]=0.f; acc[nt][3]=0.f; }

            u32 hA = pH1[i0];
            #pragma unroll
            for (int ks = 0; ks < 4; ks++) {
                u32 hB = pH1[i0 + 32];
                u32 hC = pH1[i0 + 64];
                #pragma unroll
                for (int nt = 0; nt < 2; nt++)
                    mma_f16(acc[nt], hA, hB, hB, hC, qf[nt][ks].x, qf[nt][ks].y);
                hA = hC;
                i0 += 64;
            }

            #pragma unroll
            for (int nt = 0; nt < 2; nt++) {
                int oc = nt * 8 + (lane & 3) * 2;
                float s0 = sc1[oc], h0 = sh1[oc];
                float s1 = sc1[oc + 1], h1 = sh1[oc + 1];
                float m0 = fmaxf(fmaxf(acc[nt][0] * s0 + h0, 0.f),
                                 fmaxf(acc[nt][2] * s0 + h0, 0.f));
                float m1 = fmaxf(fmaxf(acc[nt][1] * s1 + h1, 0.f),
                                 fmaxf(acc[nt][3] * s1 + h1, 0.f));
                m0 = fmaxf(m0, __shfl_xor_sync(0xFFFFFFFFu, m0, 4));
                m1 = fmaxf(m1, __shfl_xor_sync(0xFFFFFFFFu, m1, 4));
                if (!(r & 1)) {
                    int px = (x0 + r) >> 1;
                    if (px < P1) {
                        if (oc < C1) {
                            int e = oc * 928 + py * 32 + px;
                            u16 hv = f16_bits(m0);
                            pP16[e] = hv;
                            if (e > 0) pP16[13920 + e - 1] = hv;
                        }
                        if (oc + 1 < C1) {
                            int e = (oc + 1) * 928 + py * 32 + px;
                            u16 hv = f16_bits(m1);
                            pP16[e] = hv;
                            pP16[13920 + e - 1] = hv;
                        }
                    }
                }
            }
        }
    }
    __syncthreads();

    // ---- phase 3: conv2 MMA (64 accums, pipelined frag loads; R15 style) ----
    int c0[4], c1[4];
    #pragma unroll
    for (int i = 0; i < 4; i++) {
        int mt = w * 4 + i; if (mt > 30) mt = 30;
        int p0 = mt * 16 + (lane >> 2); if (p0 > 483) p0 = 483;
        int p1 = p0 + 8;                if (p1 > 483) p1 = 483;
        int y0 = p0 / 22, x0 = p0 - y0 * 22;
        int y1 = p1 / 22, x1 = p1 - y1 * 22;
        int dx0 = (lane & 3) * 2;
        c0[i] = (x0 & 1) * PL2 + y0 * 16 + ((x0 + dx0 - (x0 & 1)) >> 1);
        c1[i] = (x1 & 1) * PL2 + y1 * 16 + ((x1 + dx0 - (x1 & 1)) >> 1);
    }

    float acc[4][4][4];
    #pragma unroll
    for (int i = 0; i < 4; i++)
        #pragma unroll
        for (int n = 0; n < 4; n++)
            { acc[i][n][0]=0.f; acc[i][n][1]=0.f; acc[i][n][2]=0.f; acc[i][n][3]=0.f; }

    uint2 q0 = g_Bfrag2[0 * 32 + lane];
    uint2 q1 = g_Bfrag2[1 * 32 + lane];
    uint2 q2 = g_Bfrag2[2 * 32 + lane];
    uint2 q3 = g_Bfrag2[3 * 32 + lane];

    #pragma unroll 1
    for (int j = 0; j < NKS2; j++) {
        const int kb0 = rowTab[2 * j];
        const int kb1 = rowTab[2 * j + 1];
        uint2 n0, n1, n2, n3;
        if (j + 1 < NKS2) {
            n0 = g_Bfrag2[((j + 1) * 4 + 0) * 32 + lane];
            n1 = g_Bfrag2[((j + 1) * 4 + 1) * 32 + lane];
            n2 = g_Bfrag2[((j + 1) * 4 + 2) * 32 + lane];
            n3 = g_Bfrag2[((j + 1) * 4 + 3) * 32 + lane];
        }
        #pragma unroll
        for (int i = 0; i < 4; i++) {
            u32 ah0 = pH2[c0[i] + kb0], ah1 = pH2[c1[i] + kb0];
            u32 ah2 = pH2[c0[i] + kb1], ah3 = pH2[c1[i] + kb1];
            mma_f16(acc[i][0], ah0, ah1, ah2, ah3, q0.x, q0.y);
            mma_f16(acc[i][1], ah0, ah1, ah2, ah3, q1.x, q1.y);
            mma_f16(acc[i][2], ah0, ah1, ah2, ah3, q2.x, q2.y);
            mma_f16(acc[i][3], ah0, ah1, ah2, ah3, q3.x, q3.y);
        }
        q0 = n0; q1 = n1; q2 = n2; q3 = n3;
    }

    __syncthreads();                       // planes dead; reuse as u16 stage
    u16* stg = (u16*)(smem + MM_P);        // [484][33] u16
    #pragma unroll
    for (int i = 0; i < 4; i++) {
        int mt = w * 4 + i; if (mt > 30) mt = 30;
        int r0 = mt * 16 + (lane >> 2), r1 = r0 + 8;
        #pragma unroll
        for (int n = 0; n < 4; n++) {
            int oc = n * 8 + (lane & 3) * 2;
            if (oc < C2) {
                float s0 = sc2[oc], h0 = sh2[oc];
                float s1 = sc2[oc + 1], h1 = sh2[oc + 1];
                if (r0 < 484) {
                    stg[r0 * 33 + oc]     = f16_bits(fmaxf(acc[i][n][0] * s0 + h0, 0.f));
                    stg[r0 * 33 + oc + 1] = f16_bits(fmaxf(acc[i][n][1] * s1 + h1, 0.f));
                }
                if (r1 < 484) {
                    stg[r1 * 33 + oc]     = f16_bits(fmaxf(acc[i][n][2] * s0 + h0, 0.f));
                    stg[r1 * 33 + oc + 1] = f16_bits(fmaxf(acc[i][n][3] * s1 + h1, 0.f));
                }
            }
        }
    }
    __syncthreads();
    // ---- phase 4: 2x2 pool -> fc1 input (fp16) ----
    for (int i = t; i < 3630; i += 256) {
        int oc = i / 121, pos = i % 121;
        int py = pos / 11, px = pos % 11;
        int p00 = (2 * py) * 22 + 2 * px;
        float v = fmaxf(fmaxf(f16_val(stg[p00 * 33 + oc]),
                              f16_val(stg[(p00 + 1) * 33 + oc])),
                        fmaxf(f16_val(stg[(p00 + 22) * 33 + oc]),
                              f16_val(stg[(p00 + 23) * 33 + oc])));
        g_p2h[(size_t)b * FC1_IN + i] = f16_bits(v);
    }
}

// ---------------- kernel 2: FC1 via fp16 mma (1-term, K-split 8) ----------------
__global__ __launch_bounds__(256, 1) void fc1_mma_kernel()
{
    const int t = threadIdx.x, w = t >> 5, lane = t & 31;
    const int mt = blockIdx.x;
    const int kz = blockIdx.y;

    const int row0 = mt * 128 + w * 16 + (lane >> 2);
    const size_t base0 = (size_t)row0 * FC1_IN;
    const size_t base1 = (size_t)(row0 + 8) * FC1_IN;
    const int koff = (lane & 3) * 2;

    const int ks0 = kz * 28 + (kz < 3 ? kz : 3);
    const int nks = 28 + (kz < 3 ? 1 : 0);

    float acc[25][4];
    #pragma unroll
    for (int n = 0; n < 25; n++)
        { acc[n][0]=0.f; acc[n][1]=0.f; acc[n][2]=0.f; acc[n][3]=0.f; }

    #pragma unroll 1
    for (int ks = ks0; ks < ks0 + nks; ks++) {
        const int k0 = ks * 16 + koff;
        u32 ah0 = *(const u32*)&g_p2h[base0 + k0];
        u32 ah1 = *(const u32*)&g_p2h[base1 + k0];
        u32 ah2 = *(const u32*)&g_p2h[base0 + k0 + 8];
        u32 ah3 = *(const u32*)&g_p2h[base1 + k0 + 8];
        const uint2* bp = &g_W1frag[(size_t)ks * 25 * 32 + lane];
        #pragma unroll
        for (int n = 0; n < 25; n++) {
            uint2 q = bp[n * 32];
            mma_f16(acc[n], ah0, ah1, ah2, ah3, q.x, q.y);
        }
    }

    float* dst = g_fc1p + (size_t)kz * B * FC1_OUT;
    const int r0 = row0, r1 = row0 + 8;
    #pragma unroll
    for (int n = 0; n < 25; n++) {
        int o = n * 8 + (lane & 3) * 2;
        dst[(size_t)r0 * FC1_OUT + o]     = acc[n][0];
        dst[(size_t)r0 * FC1_OUT + o + 1] = acc[n][1];
        dst[(size_t)r1 * FC1_OUT + o]     = acc[n][2];
        dst[(size_t)r1 * FC1_OUT + o + 1] = acc[n][3];
    }
}

// ---------------- kernel 3: FC2 + sigmoid ----------------
__global__ __launch_bounds__(256) void fc2_kernel(
    const float* __restrict__ fc1b,
    const float* __restrict__ w2, const float* __restrict__ b2,
    float* __restrict__ out)
{
    const int warp = threadIdx.x >> 5, lane = threadIdx.x & 31;
    const int b = blockIdx.x * 8 + warp;
    const size_t PS = (size_t)B * FC1_OUT;
    const float* base = g_fc1p + (size_t)b * FC1_OUT;
    float s0 = 0.f, s1 = 0.f;
    for (int o = lane; o < FC1_OUT; o += 32) {
        float v = fc1b[o];
        #pragma unroll
        for (int p = 0; p < KSPLIT; p++)
            v += base[p * PS + o];
        v = fmaxf(v, 0.f);
        s0 += v * w2[o];
        s1 += v * w2[FC1_OUT + o];
    }
    #pragma unroll
    for (int d = 16; d > 0; d >>= 1) {
        s0 += __shfl_xor_sync(0xFFFFFFFFu, s0, d);
        s1 += __shfl_xor_sync(0xFFFFFFFFu, s1, d);
    }
    if (lane == 0) {
        out[2 * b + 0] = 1.f / (1.f + expf(-(s0 + b2[0])));
        out[2 * b + 1] = 1.f / (1.f + expf(-(s1 + b2[1])));
    }
}

// ---------------- launch ----------------
extern "C" void kernel_launch(void* const* d_in, const int* in_sizes, int n_in,
                              void* d_out, int out_size)
{
    const float* x       = (const float*)d_in[0];
    const float* log_s   = (const float*)d_in[1];
    const float* log_a   = (const float*)d_in[2];
    const float* log_d   = (const float*)d_in[3];
    const float* log_r   = (const float*)d_in[4];
    const float* conv1_w = (const float*)d_in[5];
    const float* conv1_b = (const float*)d_in[6];
    const float* bn1_g   = (const float*)d_in[7];
    const float* bn1_b   = (const float*)d_in[8];
    const float* bn1_m   = (const float*)d_in[9];
    const float* bn1_v   = (const float*)d_in[10];
    const float* conv2_w = (const float*)d_in[11];
    const float* conv2_b = (const float*)d_in[12];
    const float* bn2_g   = (const float*)d_in[13];
    const float* bn2_b   = (const float*)d_in[14];
    const float* bn2_m   = (const float*)d_in[15];
    const float* bn2_v   = (const float*)d_in[16];
    const float* fc1_w   = (const float*)d_in[17];
    const float* fc1_b   = (const float*)d_in[18];
    const float* fc2_w   = (const float*)d_in[19];
    const float* fc2_b   = (const float*)d_in[20];
    float* out = (float*)d_out;

    static int smem_set = 0;
    if (!smem_set) {
        cudaFuncSetAttribute(conv_fused_kernel,
                             cudaFuncAttributeMaxDynamicSharedMemorySize, MM_TOT);
        smem_set = 1;
    }

    const int prep_total = NFC1 + NKS2 * 128 + 256;
    prep_all_frags<<<(prep_total + 255) / 256, 256>>>(conv1_w, conv2_w, fc1_w);
    conv_fused_kernel<<<B, 256, MM_TOT>>>(x, log_s, log_a, log_d, log_r,
                                          conv1_b, bn1_g, bn1_b, bn1_m, bn1_v,
                                          conv2_b, bn2_g, bn2_b, bn2_m, bn2_v);
    fc1_mma_kernel<<<dim3(16, KSPLIT), 256>>>();
    fc2_kernel<<<B / 8, 256>>>(fc1_b, fc2_w, fc2_b, out);
}